// round 1
// baseline (speedup 1.0000x reference)
#include <cuda_runtime.h>
#include <math.h>
#include <stdint.h>

// ---------------- problem constants ----------------
#define VOCAB     151936
#define BATCH     3
#define TOPK      3
#define BEAMS     3
#define HIST      64
#define CHUNKS    32
#define CHUNK_LEN (VOCAB / CHUNKS)        // 4748, exact: 32*4748 = 151936

// kv: (L=28, B=3, H=16, S=1024, D=128) f32
#define KV_ELEMS   176160768              // 28*3*16*1024*128
#define CHUNK_F    2097152                // 16*1024*128 (floats per (l,b) slab)
#define CHUNK4     524288                 // CHUNK_F/4 = 2^19
#define TOTAL4     44040192               // KV_ELEMS/4

// output layout (flattened tuple, concatenated, float32):
// kv_out | tok_col(3) | save_id_out(3*65) | rp(3*V) | top_beam_prob(3) | max_logits_idx(1)
#define OFF_TOK   176160768u
#define OFF_SAVE  176160771u
#define OFF_RP    176160966u
#define OFF_PROB  176616774u
#define OFF_MAX   176616777u

// ---------------- device scratch (no allocs allowed) ----------------
__device__ float g_pm[BATCH][CHUNKS];          // partial running max
__device__ float g_ps[BATCH][CHUNKS];          // partial scaled sum
__device__ float g_pval[BATCH][CHUNKS][TOPK];  // partial top-3 values
__device__ int   g_pidx[BATCH][CHUNKS][TOPK];  // partial top-3 indices
__device__ int   g_beam_index[BEAMS];
__device__ int   g_tokens[BEAMS];

// ---------------- helpers ----------------
struct Top3 { float v[3]; int i[3]; };

__device__ __forceinline__ void top3_init(Top3& t) {
#pragma unroll
    for (int k = 0; k < 3; k++) { t.v[k] = -INFINITY; t.i[k] = 0x7fffffff; }
}

// JAX top_k semantics: descending values, ties -> smaller index first
__device__ __forceinline__ void top3_insert(Top3& t, float v, int idx) {
    if (v > t.v[0] || (v == t.v[0] && idx < t.i[0])) {
        t.v[2] = t.v[1]; t.i[2] = t.i[1];
        t.v[1] = t.v[0]; t.i[1] = t.i[0];
        t.v[0] = v;      t.i[0] = idx;
    } else if (v > t.v[1] || (v == t.v[1] && idx < t.i[1])) {
        t.v[2] = t.v[1]; t.i[2] = t.i[1];
        t.v[1] = v;      t.i[1] = idx;
    } else if (v > t.v[2] || (v == t.v[2] && idx < t.i[2])) {
        t.v[2] = v;      t.i[2] = idx;
    }
}

// ---------------- kernel 1: per-chunk partial top-3 + logsumexp ----------------
__global__ void topk_partial(const float* __restrict__ logits,
                             const float* __restrict__ rp) {
    int b = blockIdx.x / CHUNKS;
    int c = blockIdx.x % CHUNKS;
    int start = c * CHUNK_LEN;
    const float* lg = logits + (size_t)b * VOCAB;
    const float* rb = rp     + (size_t)b * VOCAB;

    Top3 t; top3_init(t);
    float m = -INFINITY, s = 0.f;

    for (int j = threadIdx.x; j < CHUNK_LEN; j += blockDim.x) {
        int v = start + j;
        float x = lg[v] * rb[v];
        if (x > m) { s = s * __expf(m - x) + 1.f; m = x; }
        else       { s += __expf(x - m); }
        top3_insert(t, x, v);
    }

    // warp butterfly merge
#pragma unroll
    for (int off = 16; off > 0; off >>= 1) {
        float om  = __shfl_xor_sync(0xffffffffu, m,      off);
        float os  = __shfl_xor_sync(0xffffffffu, s,      off);
        float ov0 = __shfl_xor_sync(0xffffffffu, t.v[0], off);
        float ov1 = __shfl_xor_sync(0xffffffffu, t.v[1], off);
        float ov2 = __shfl_xor_sync(0xffffffffu, t.v[2], off);
        int   oi0 = __shfl_xor_sync(0xffffffffu, t.i[0], off);
        int   oi1 = __shfl_xor_sync(0xffffffffu, t.i[1], off);
        int   oi2 = __shfl_xor_sync(0xffffffffu, t.i[2], off);
        float nm = fmaxf(m, om);
        s = s * __expf(m - nm) + os * __expf(om - nm);
        m = nm;
        top3_insert(t, ov0, oi0);
        top3_insert(t, ov1, oi1);
        top3_insert(t, ov2, oi2);
    }

    __shared__ float sv[8][3]; __shared__ int si[8][3];
    __shared__ float smx[8];   __shared__ float ssm[8];
    int warp = threadIdx.x >> 5, lane = threadIdx.x & 31;
    if (lane == 0) {
#pragma unroll
        for (int k = 0; k < 3; k++) { sv[warp][k] = t.v[k]; si[warp][k] = t.i[k]; }
        smx[warp] = m; ssm[warp] = s;
    }
    __syncthreads();

    if (threadIdx.x == 0) {
        Top3 f; top3_init(f);
        float fm = -INFINITY, fs = 0.f;
        int nw = (blockDim.x + 31) >> 5;
        for (int w = 0; w < nw; w++) {
            float nm = fmaxf(fm, smx[w]);
            fs = fs * __expf(fm - nm) + ssm[w] * __expf(smx[w] - nm);
            fm = nm;
#pragma unroll
            for (int k = 0; k < 3; k++) top3_insert(f, sv[w][k], si[w][k]);
        }
        g_pm[b][c] = fm; g_ps[b][c] = fs;
#pragma unroll
        for (int k = 0; k < 3; k++) { g_pval[b][c][k] = f.v[k]; g_pidx[b][c][k] = f.i[k]; }
    }
}

// ---------------- kernel 2: merge partials, beam combine, small outputs ----------------
__global__ void combine_kernel(const float* __restrict__ prev_prob,
                               const int*   __restrict__ save_id,
                               float* __restrict__ out) {
    __shared__ int s_beam[BEAMS], s_tok[BEAMS];

    if (threadIdx.x == 0) {
        float fv[BATCH][3]; int fi[BATCH][3]; float flse[BATCH];
        for (int b = 0; b < BATCH; b++) {
            Top3 t; top3_init(t);
            float m = -INFINITY, s = 0.f;
            for (int c = 0; c < CHUNKS; c++) {
                float pm = g_pm[b][c], ps = g_ps[b][c];
                float nm = fmaxf(m, pm);
                s = s * __expf(m - nm) + ps * __expf(pm - nm);
                m = nm;
#pragma unroll
                for (int k = 0; k < 3; k++) top3_insert(t, g_pval[b][c][k], g_pidx[b][c][k]);
            }
            flse[b] = m + logf(s);
#pragma unroll
            for (int k = 0; k < 3; k++) { fv[b][k] = t.v[k]; fi[b][k] = t.i[k]; }
        }

        // 9 candidates: (topk_prob + previous_prob), flat index order
        float cand[BATCH * TOPK];
        for (int b = 0; b < BATCH; b++)
            for (int k = 0; k < TOPK; k++)
                cand[b * TOPK + k] = (fv[b][k] - flse[b]) + prev_prob[b];

        Top3 beam; top3_init(beam);
        for (int j = 0; j < BATCH * TOPK; j++) top3_insert(beam, cand[j], j);

        for (int i = 0; i < BEAMS; i++) {
            int fl = beam.i[i];
            int bi = fl / TOPK;
            int tk = fi[bi][fl % TOPK];
            s_beam[i] = bi;       s_tok[i] = tk;
            g_beam_index[i] = bi; g_tokens[i] = tk;
            out[OFF_TOK  + i] = (float)tk;
            out[OFF_PROB + i] = beam.v[i];
        }
        out[OFF_MAX] = (float)s_tok[0];
    }
    __syncthreads();

    // save_id_out: (3, 65) = gathered history + new token
    for (int i = threadIdx.x; i < BEAMS * (HIST + 1); i += blockDim.x) {
        int r = i / (HIST + 1), c = i % (HIST + 1);
        float v = (c < HIST) ? (float)save_id[s_beam[r] * HIST + c] : (float)s_tok[r];
        out[OFF_SAVE + i] = v;
    }
}

// ---------------- kernel 3: repeat_penality gather + token multiply ----------------
__global__ void rp_kernel(const float* __restrict__ rp,
                          const float* __restrict__ pen,
                          float* __restrict__ out) {
    int i = blockIdx.x * blockDim.x + threadIdx.x;
    if (i >= BEAMS * VOCAB) return;
    int b = i / VOCAB;
    int v = i - b * VOCAB;
    float val = rp[(size_t)g_beam_index[b] * VOCAB + v];
    if (v == g_tokens[b]) val *= pen[0];
    out[OFF_RP + i] = val;
}

// ---------------- kernel 4: the big KV gather-copy (float4, MLP=4) ----------------
__global__ void kv_copy(const float4* __restrict__ src, float4* __restrict__ dst) {
    int base = blockIdx.x * (blockDim.x * 4) + threadIdx.x;  // 1024 float4 per block
    int o4[4], si4[4];
    float4 r[4];
#pragma unroll
    for (int k = 0; k < 4; k++) {
        o4[k] = base + k * 256;
        int lb = o4[k] >> 19;         // (l*3 + b), chunk4 = 2^19
        int b  = lb % 3;
        si4[k] = o4[k] + (g_beam_index[b] - b) * CHUNK4;
    }
#pragma unroll
    for (int k = 0; k < 4; k++) r[k] = src[si4[k]];
#pragma unroll
    for (int k = 0; k < 4; k++) dst[o4[k]] = r[k];
}

// ---------------- launch ----------------
extern "C" void kernel_launch(void* const* d_in, const int* in_sizes, int n_in,
                              void* d_out, int out_size) {
    const float* kv      = (const float*)d_in[0];
    const float* logits  = (const float*)d_in[1];
    const int*   save_id = (const int*)d_in[2];
    const float* rp      = (const float*)d_in[3];
    const float* prev    = (const float*)d_in[4];
    const float* pen     = (const float*)d_in[5];
    float* out = (float*)d_out;

    topk_partial  <<<BATCH * CHUNKS, 256>>>(logits, rp);
    combine_kernel<<<1, 256>>>(prev, save_id, out);
    rp_kernel     <<<(BEAMS * VOCAB + 255) / 256, 256>>>(rp, pen, out);
    kv_copy       <<<TOTAL4 / 1024, 256>>>((const float4*)kv, (float4*)out);
}